// round 14
// baseline (speedup 1.0000x reference)
#include <cuda_runtime.h>

// Problem constants
#define BB 4
#define TT 2048
#define NE 32
#define NH 8
#define NB 512                      // 4-row blocks per (b,h)
#define NSLICE 64                   // xpart slices per batch (32 rows each)
#define ROWS_B 16                   // kernel B rows per CTA
#define THR_B 256                   // 8 warps = 8 heads; lanes = 16 rows x 2 halves
#define NCTA_B ((BB * TT) / ROWS_B) // 512

// g_xpart[b][s][c*32+e] = sum over slice-s rows with (row%4==c) of x[row][e]
__device__ __align__(16) float g_xpart[BB][NSLICE][128];

__device__ __forceinline__ float clip100(float v) {
    return fminf(fmaxf(v, -100.0f), 100.0f);
}

// -------- Kernel A: partial column sums of x, bucketed by (row % 4) --------
__global__ __launch_bounds__(128) void xpart_kernel(const float* __restrict__ x)
{
    const int b   = blockIdx.x >> 6;
    const int s   = blockIdx.x & 63;
    const int tid = threadIdx.x;

    const float* xs0 = x + ((size_t)b * TT + (size_t)s * 32) * NE;
    float acc = 0.0f;
    #pragma unroll
    for (int j = 0; j < 8; ++j) acc += xs0[j * 128 + tid];
    g_xpart[b][s][tid] = acc;
}

// -------- Kernel B --------
// 256 threads = 8 warps (w = head). Lane l: row r = l&15, half = l>>4.
// Each thread computes q/z outputs {4w+2*half, 4w+2*half+1}.
// Warps 0-3 also own Vbar bucket c = w (shuffle G build, Wv/Wp from gmem).
__global__ __launch_bounds__(THR_B, 3) void rxtx_attn_kernel(
    const float* __restrict__ x,
    const float* __restrict__ Wq, const float* __restrict__ bq,
    const float* __restrict__ Wv, const float* __restrict__ bv,
    const float* __restrict__ Wp, const float* __restrict__ bp,
    float* __restrict__ out)
{
    __shared__ __align__(16) float sWq[NE][NE];    // 128B rows; float4 broadcasts
    __shared__ __align__(16) float sGT[NE][36];    // G transposed
    __shared__ float sbq[NE];
    __shared__ float sbp[NE];
    __shared__ __align__(16) float sXh8[8][128];   // xpart partials
    __shared__ __align__(16) float sX[ROWS_B][36]; // x rows
    __shared__ __align__(16) float sQ[ROWS_B][36]; // q
    __shared__ __align__(16) float sP[ROWS_B][36]; // softmax probs
    // ~19.5 KB/CTA

    const int tid  = threadIdx.x;
    const int w    = tid >> 5;            // warp = head
    const int l    = tid & 31;
    const int r    = l & 15;              // row within CTA
    const int half = l >> 4;
    const int oA   = 4 * w + 2 * half;    // first owned output column
    const int tg0  = blockIdx.x * ROWS_B;
    const int b    = tg0 >> 11;           // 128 CTAs per batch, aligned

    // ================= Phase 0: stage (vectorized) =================
    {
        const int ro = tid >> 3, cg = (tid & 7) * 4;    // 256 float4s = 32x32
        *(float4*)&sWq[ro][cg] = ((const float4*)Wq)[tid];
    }
    if (tid < 128) {                                    // 128 float4s = 16 rows
        const int ro = tid >> 3, cg = (tid & 7) * 4;
        *(float4*)&sX[ro][cg] = ((const float4*)(x + (size_t)tg0 * NE))[tid];
    } else {
        const int t2 = tid - 128;
        if (t2 < NE)          sbq[t2]      = bq[t2];
        else if (t2 < 2 * NE) sbp[t2 - NE] = bp[t2 - NE];
    }
    // xpart partial reduce: warp w sums its 8 slices, float4 per lane
    {
        const int fb = l * 4;
        float4 ps = make_float4(0.f, 0.f, 0.f, 0.f);
        #pragma unroll
        for (int s = 0; s < 8; ++s) {
            const float4 v = *(const float4*)&g_xpart[b][w * 8 + s][fb];
            ps.x += v.x; ps.y += v.y; ps.z += v.z; ps.w += v.w;
        }
        *(float4*)&sXh8[w][fb] = ps;
    }
    __syncthreads();

    // ===== Phase 1: q matvec (2 outputs/thread, streaming accumulation) =====
    {
        float a0 = sbq[oA], a1 = sbq[oA + 1];
        const float4* xrow = (const float4*)&sX[r][0];
        const float4* w0p  = (const float4*)&sWq[oA][0];
        const float4* w1p  = (const float4*)&sWq[oA + 1][0];
        #pragma unroll
        for (int k = 0; k < 8; ++k) {
            const float4 xv = xrow[k];          // bcast pairs, conflict-free
            const float4 w0 = w0p[k];           // 16-lane bcast
            const float4 w1 = w1p[k];
            a0 += xv.x * w0.x + xv.y * w0.y + xv.z * w0.z + xv.w * w0.w;
            a1 += xv.x * w1.x + xv.y * w1.y + xv.z * w1.z + xv.w * w1.w;
        }
        *(float2*)&sQ[r][oA] = make_float2(clip100(a0), clip100(a1));
    }

    // ===== Vbar + G build (warps 0-3; Wv/Wp straight from L2) =====
    if (w < 4) {
        const int c = w;
        float xb = 0.0f;
        #pragma unroll
        for (int sg = 0; sg < 8; ++sg) xb += sXh8[sg][c * 32 + l];
        xb *= (1.0f / (float)NB);
        // Vb[c][o], o = lane: shuffle-dot against global Wv row l
        float acc = bv[l];
        const float4* wvrow = (const float4*)(Wv + l * NE);
        #pragma unroll
        for (int k = 0; k < 8; ++k) {
            const float4 v = __ldg(&wvrow[k]);
            acc += __shfl_sync(0xffffffffu, xb, 4 * k + 0) * v.x
                 + __shfl_sync(0xffffffffu, xb, 4 * k + 1) * v.y
                 + __shfl_sync(0xffffffffu, xb, 4 * k + 2) * v.z
                 + __shfl_sync(0xffffffffu, xb, 4 * k + 3) * v.w;
        }
        // G[h*4+c][o] = sum_d Vb[c][h*4+d]*Wp[o][h*4+d]; store transposed
        const float4* wprow = (const float4*)(Wp + l * NE);
        #pragma unroll
        for (int h2 = 0; h2 < NH; ++h2) {
            const float4 pv = __ldg(&wprow[h2]);
            const float gv =
                  __shfl_sync(0xffffffffu, acc, h2 * 4 + 0) * pv.x
                + __shfl_sync(0xffffffffu, acc, h2 * 4 + 1) * pv.y
                + __shfl_sync(0xffffffffu, acc, h2 * 4 + 2) * pv.z
                + __shfl_sync(0xffffffffu, acc, h2 * 4 + 3) * pv.w;
            sGT[l][h2 * 4 + c] = gv;
        }
    }
    __syncwarp();   // RXTX reads both halves' sQ entries (same warp)

    // ================= Phase 2: RXTX + 4-way softmax =================
    {
        const int o0  = 4 * w;
        const int blk = r & ~3;
        const int rr  = r & 3;
        const float4 q0 = *(const float4*)&sQ[blk + 0][o0];
        const float4 q1 = *(const float4*)&sQ[blk + 1][o0];
        const float4 q2 = *(const float4*)&sQ[blk + 2][o0];
        const float4 q3 = *(const float4*)&sQ[blk + 3][o0];
        const float X1 = q0.x,  X2 = q0.y,  X3 = q0.z,  X4 = q0.w;
        const float X5 = q1.x,  X6 = q1.y,  X7 = q1.z,  X8 = q1.w;
        const float X9 = q2.x,  X10 = q2.y, X11 = q2.z, X12 = q2.w;
        const float X13 = q3.x, X14 = q3.y, X15 = q3.z, X16 = q3.w;

        const float m1  = (-X2 + X3 - X4 + X8) * (X8 + X11);
        const float m2  = (X1 - X5 - X6 + X7) * (X15 + X5);
        const float m3  = (-X2 + X12) * (-X10 + X16 + X12);
        const float m4  = (X9 - X6) * (X13 + X9 - X14);
        const float m5  = (X2 + X11) * (-X6 + X15 - X7);
        const float m6  = (X6 + X11) * (X6 + X7 - X11);
        const float m7  = X11 * (X6 + X7);
        const float m8  = X2 * (-X14 - X10 + X6 - X15 + X7 + X16 + X12);
        const float m9  = X6 * (X13 + X9 - X14 - X10 + X6 + X7 - X11);
        const float m10 = (X2 - X3 + X7 + X11 + X4 - X8) * X11;
        const float m11 = (X5 + X6 - X7) * X5;
        const float m12 = (X2 - X3 + X4) * X8;
        const float m13 = (-X1 + X5 + X6 + X3 - X7 + X11) * X15;
        const float m14 = (-X1 + X5 + X6) * (X13 + X9 + X15);
        const float m15 = (X2 + X4 - X8) * (X11 + X16 + X12);
        const float m16 = (X1 - X8) * (X9 - X16);
        const float m17 = X12 * (X10 - X12);
        const float m18 = X9 * (X13 - X14);
        const float m19 = (-X2 + X3) * (-X15 + X7 + X8);
        const float m20 = (X5 + X9 - X8) * X9;
        const float m21 = X8 * (X9 - X8 + X12);
        const float m22 = (-X6 + X7) * (X5 + X7 - X11);
        const float m23 = X1 * (X13 - X5 + X16);
        const float m24 = (-X1 + X4 + X12) * X16;
        const float m25 = (X9 + X2 + X10) * X14;
        const float m26 = (X6 + X10 + X12) * X10;

        const float z1 = m7 - m11 - m12;
        const float z2 = m1 + m12 + m21;
        const float z3 = m3 + m17 - m24;
        const float z4 = m2 + m11 + m23;
        const float z5 = m5 + m7 + m8;
        const float z6 = m4 - m18 - m20;
        const float z7 = m6 - m7 - m9;
        const float z8 = m17 + m18;

        const float c01 = m2 - m5 - z1 + m13 + m19;
        const float c02 = z2 + z3 + m15 + m16;
        const float c03 = z4 - z3 - z5 - m13;
        const float c11 = m1 + m6 - z1 + m10 + m22;
        const float c12 = z2 - z6 + z7 + m10;
        const float c13 = z4 + z6 + m14 + m16;
        const float c22 = m4 - z7 - z8 + m26;
        const float c23 = m3 + z5 + z8 + m25;

        float a0, a1, a2, a3;
        if      (rr == 0) { a0 = 0.0f; a1 = c01;  a2 = c02;  a3 = c03;  }
        else if (rr == 1) { a0 = c01;  a1 = c11;  a2 = c12;  a3 = c13;  }
        else if (rr == 2) { a0 = c02;  a1 = c12;  a2 = c22;  a3 = c23;  }
        else              { a0 = c03;  a1 = c13;  a2 = c23;  a3 = 0.0f; }

        a0 = clip100(a0) * 0.5f;
        a1 = clip100(a1) * 0.5f;
        a2 = clip100(a2) * 0.5f;
        a3 = clip100(a3) * 0.5f;

        const float mx = fmaxf(fmaxf(a0, a1), fmaxf(a2, a3));
        const float e0 = __expf(a0 - mx);
        const float e1 = __expf(a1 - mx);
        const float e2 = __expf(a2 - mx);
        const float e3 = __expf(a3 - mx);
        const float inv = 1.0f / (e0 + e1 + e2 + e3);

        // half-0 lanes store the full prob row (conflict-free STS.128)
        if (half == 0)
            *(float4*)&sP[r][o0] =
                make_float4(e0 * inv, e1 * inv, e2 * inv, e3 * inv);
    }
    __syncthreads();   // covers sP (all warps) and sGT (warps 0-3)

    // ===== Phase 3: z (2 outputs/thread, streaming) + direct store =====
    {
        float a0 = sbp[oA], a1 = sbp[oA + 1];
        const float4* prow = (const float4*)&sP[r][0];
        const float4* g0p  = (const float4*)&sGT[oA][0];
        const float4* g1p  = (const float4*)&sGT[oA + 1][0];
        #pragma unroll
        for (int k = 0; k < 8; ++k) {
            const float4 pv = prow[k];
            const float4 g0 = g0p[k];
            const float4 g1 = g1p[k];
            a0 += pv.x * g0.x + pv.y * g0.y + pv.z * g0.z + pv.w * g0.w;
            a1 += pv.x * g1.x + pv.y * g1.y + pv.z * g1.z + pv.w * g1.w;
        }
        // direct 8B store: row tg0+r, cols [oA, oA+2)
        *(float2*)(out + ((size_t)(tg0 + r)) * NE + oA) = make_float2(a0, a1);
    }
}

extern "C" void kernel_launch(void* const* d_in, const int* in_sizes, int n_in,
                              void* d_out, int out_size)
{
    // metadata order: x, Wq, bq, Wk, bk, Wv, bv, Wp, bp   (Wk/bk dead)
    const float* x  = (const float*)d_in[0];
    const float* Wq = (const float*)d_in[1];
    const float* bq = (const float*)d_in[2];
    const float* Wv = (const float*)d_in[5];
    const float* bv = (const float*)d_in[6];
    const float* Wp = (const float*)d_in[7];
    const float* bp = (const float*)d_in[8];
    float* out = (float*)d_out;

    xpart_kernel<<<BB * NSLICE, 128>>>(x);
    rxtx_attn_kernel<<<NCTA_B, THR_B>>>(x, Wq, bq, Wv, bv, Wp, bp, out);
}

// round 15
// speedup vs baseline: 1.6562x; 1.6562x over previous
#include <cuda_runtime.h>

// Problem constants
#define BB 4
#define TT 2048
#define NE 32
#define NH 8
#define NB 512                      // 4-row blocks per (b,h)
#define NSLICE 64                   // xpart slices per batch (32 rows each)
#define ROWS_B 32                   // kernel B rows per CTA
#define THR_B 256                   // 8 warps: warp = head, lane = row
#define NCTA_B ((BB * TT) / ROWS_B) // 256

// g_xpart[b][s][c*32+e] = sum over slice-s rows with (row%4==c) of x[row][e]
__device__ __align__(16) float g_xpart[BB][NSLICE][128];

__device__ __forceinline__ float clip100(float v) {
    return fminf(fmaxf(v, -100.0f), 100.0f);
}
__device__ __forceinline__ void griddep_wait() {
    asm volatile("griddepcontrol.wait;" ::: "memory");
}
__device__ __forceinline__ void griddep_launch_dependents() {
    asm volatile("griddepcontrol.launch_dependents;");
}

// -------- Kernel A: partial column sums of x, bucketed by (row % 4) --------
__global__ __launch_bounds__(128) void xpart_kernel(const float* __restrict__ x)
{
    const int b   = blockIdx.x >> 6;
    const int s   = blockIdx.x & 63;
    const int tid = threadIdx.x;

    const float* xs0 = x + ((size_t)b * TT + (size_t)s * 32) * NE;
    float acc = 0.0f;
    #pragma unroll
    for (int j = 0; j < 8; ++j) acc += xs0[j * 128 + tid];
    g_xpart[b][s][tid] = acc;

    __threadfence();                 // partials visible to dependent grid
    griddep_launch_dependents();
}

// -------- Kernel B: q, RXTX, softmax; LATE Vbar/G (PDL wait post-softmax) ----
// 256 threads = 8 warps (w = head) x 32 lanes (l = row).
__global__ __launch_bounds__(THR_B, 2) void rxtx_attn_kernel(
    const float* __restrict__ x,
    const float* __restrict__ Wq, const float* __restrict__ bq,
    const float* __restrict__ Wv, const float* __restrict__ bv,
    const float* __restrict__ Wp, const float* __restrict__ bp,
    float* __restrict__ out)
{
    __shared__ __align__(16) float sWq[NE][NE];   // 128B rows; float4 broadcasts
    __shared__ float sWv[NE][33];                  // per-lane rows, stride 33
    __shared__ float sWp[NE][33];
    __shared__ __align__(16) float sGT[NE][36];   // G transposed; float4 broadcasts
    __shared__ float sbq[NE];
    __shared__ float sbp[NE];
    __shared__ __align__(16) float sX[ROWS_B][36]; // x rows
    __shared__ __align__(16) float sQ[ROWS_B][36]; // q (float4 access)
    __shared__ __align__(16) float sP[ROWS_B][36]; // softmax probs

    const int tid = threadIdx.x;
    const int w   = tid >> 5;           // warp = head
    const int l   = tid & 31;           // lane = row
    const int tg0 = blockIdx.x * ROWS_B;
    const int b   = tg0 >> 11;          // 64 CTAs per batch, aligned

    // ================= Phase 0: stage everything (vectorized) =================
    // No g_xpart access here — fully independent of kernel A.
    {
        const int ro = tid >> 3, cg = (tid & 7) * 4;    // 256 float4s cover 32x32
        *(float4*)&sWq[ro][cg] = ((const float4*)Wq)[tid];
        const float4 wv = ((const float4*)Wv)[tid];
        sWv[ro][cg + 0] = wv.x; sWv[ro][cg + 1] = wv.y;
        sWv[ro][cg + 2] = wv.z; sWv[ro][cg + 3] = wv.w;
        const float4 wp = ((const float4*)Wp)[tid];
        sWp[ro][cg + 0] = wp.x; sWp[ro][cg + 1] = wp.y;
        sWp[ro][cg + 2] = wp.z; sWp[ro][cg + 3] = wp.w;
        *(float4*)&sX[ro][cg] = ((const float4*)(x + (size_t)tg0 * NE))[tid];
    }
    if (tid < NE)          sbq[tid]      = bq[tid];
    else if (tid < 2 * NE) sbp[tid - NE] = bp[tid - NE];
    __syncthreads();

    // ================= Phase 1: q matvec (all warps) =================
    const int o0 = w * 4;
    {
        float xr[NE];
        #pragma unroll
        for (int k = 0; k < 8; ++k) {                   // float4, conflict-free
            const float4 v = *(const float4*)&sX[l][k * 4];
            xr[4*k] = v.x; xr[4*k+1] = v.y; xr[4*k+2] = v.z; xr[4*k+3] = v.w;
        }
        float qv[4];
        #pragma unroll
        for (int i = 0; i < 4; ++i) {
            const int o = o0 + i;                       // warp-uniform
            const float4* wrow = (const float4*)&sWq[o][0];
            float a = sbq[o];
            #pragma unroll
            for (int k = 0; k < 8; ++k) {
                const float4 v = wrow[k];               // broadcast LDS.128
                a += xr[4*k] * v.x + xr[4*k+1] * v.y
                   + xr[4*k+2] * v.z + xr[4*k+3] * v.w;
            }
            qv[i] = clip100(a);
        }
        *(float4*)&sQ[l][o0] = make_float4(qv[0], qv[1], qv[2], qv[3]);
    }
    __syncwarp();   // RXTX only needs this warp's sQ columns

    // ================= Phase 2: RXTX + 4-way softmax =================
    {
        const int blk = l & ~3;
        const int rr  = l & 3;
        const float4 q0 = *(const float4*)&sQ[blk + 0][o0];
        const float4 q1 = *(const float4*)&sQ[blk + 1][o0];
        const float4 q2 = *(const float4*)&sQ[blk + 2][o0];
        const float4 q3 = *(const float4*)&sQ[blk + 3][o0];
        const float X1 = q0.x,  X2 = q0.y,  X3 = q0.z,  X4 = q0.w;
        const float X5 = q1.x,  X6 = q1.y,  X7 = q1.z,  X8 = q1.w;
        const float X9 = q2.x,  X10 = q2.y, X11 = q2.z, X12 = q2.w;
        const float X13 = q3.x, X14 = q3.y, X15 = q3.z, X16 = q3.w;

        const float m1  = (-X2 + X3 - X4 + X8) * (X8 + X11);
        const float m2  = (X1 - X5 - X6 + X7) * (X15 + X5);
        const float m3  = (-X2 + X12) * (-X10 + X16 + X12);
        const float m4  = (X9 - X6) * (X13 + X9 - X14);
        const float m5  = (X2 + X11) * (-X6 + X15 - X7);
        const float m6  = (X6 + X11) * (X6 + X7 - X11);
        const float m7  = X11 * (X6 + X7);
        const float m8  = X2 * (-X14 - X10 + X6 - X15 + X7 + X16 + X12);
        const float m9  = X6 * (X13 + X9 - X14 - X10 + X6 + X7 - X11);
        const float m10 = (X2 - X3 + X7 + X11 + X4 - X8) * X11;
        const float m11 = (X5 + X6 - X7) * X5;
        const float m12 = (X2 - X3 + X4) * X8;
        const float m13 = (-X1 + X5 + X6 + X3 - X7 + X11) * X15;
        const float m14 = (-X1 + X5 + X6) * (X13 + X9 + X15);
        const float m15 = (X2 + X4 - X8) * (X11 + X16 + X12);
        const float m16 = (X1 - X8) * (X9 - X16);
        const float m17 = X12 * (X10 - X12);
        const float m18 = X9 * (X13 - X14);
        const float m19 = (-X2 + X3) * (-X15 + X7 + X8);
        const float m20 = (X5 + X9 - X8) * X9;
        const float m21 = X8 * (X9 - X8 + X12);
        const float m22 = (-X6 + X7) * (X5 + X7 - X11);
        const float m23 = X1 * (X13 - X5 + X16);
        const float m24 = (-X1 + X4 + X12) * X16;
        const float m25 = (X9 + X2 + X10) * X14;
        const float m26 = (X6 + X10 + X12) * X10;

        const float z1 = m7 - m11 - m12;
        const float z2 = m1 + m12 + m21;
        const float z3 = m3 + m17 - m24;
        const float z4 = m2 + m11 + m23;
        const float z5 = m5 + m7 + m8;
        const float z6 = m4 - m18 - m20;
        const float z7 = m6 - m7 - m9;
        const float z8 = m17 + m18;

        const float c01 = m2 - m5 - z1 + m13 + m19;
        const float c02 = z2 + z3 + m15 + m16;
        const float c03 = z4 - z3 - z5 - m13;
        const float c11 = m1 + m6 - z1 + m10 + m22;
        const float c12 = z2 - z6 + z7 + m10;
        const float c13 = z4 + z6 + m14 + m16;
        const float c22 = m4 - z7 - z8 + m26;
        const float c23 = m3 + z5 + z8 + m25;

        float a0, a1, a2, a3;
        if      (rr == 0) { a0 = 0.0f; a1 = c01;  a2 = c02;  a3 = c03;  }
        else if (rr == 1) { a0 = c01;  a1 = c11;  a2 = c12;  a3 = c13;  }
        else if (rr == 2) { a0 = c02;  a1 = c12;  a2 = c22;  a3 = c23;  }
        else              { a0 = c03;  a1 = c13;  a2 = c23;  a3 = 0.0f; }

        a0 = clip100(a0) * 0.5f;
        a1 = clip100(a1) * 0.5f;
        a2 = clip100(a2) * 0.5f;
        a3 = clip100(a3) * 0.5f;

        const float mx = fmaxf(fmaxf(a0, a1), fmaxf(a2, a3));
        const float e0 = __expf(a0 - mx);
        const float e1 = __expf(a1 - mx);
        const float e2 = __expf(a2 - mx);
        const float e3 = __expf(a3 - mx);
        const float inv = 1.0f / (e0 + e1 + e2 + e3);

        *(float4*)&sP[l][o0] = make_float4(e0 * inv, e1 * inv, e2 * inv, e3 * inv);
    }

    // ===== Phase 2b: LATE Vbar + G build (warps 0-3) — kernel A long done =====
    if (w < 4) {
        const int c = w;
        griddep_wait();                 // should return immediately (~5us into B)
        // 64-slice reduce, 4 independent accumulator chains (MLP 4, L2-hot)
        float s0 = 0.f, s1 = 0.f, s2 = 0.f, s3 = 0.f;
        const float* gp = &g_xpart[b][0][c * 32 + l];
        #pragma unroll
        for (int s = 0; s < NSLICE; s += 4) {
            s0 += gp[(s + 0) * 128];
            s1 += gp[(s + 1) * 128];
            s2 += gp[(s + 2) * 128];
            s3 += gp[(s + 3) * 128];
        }
        const float xb = ((s0 + s1) + (s2 + s3)) * (1.0f / (float)NB);
        // Vb[c][o] with o = lane: shuffle-dot against Wv rows
        float acc = bv[l];
        #pragma unroll
        for (int e = 0; e < NE; ++e)
            acc += __shfl_sync(0xffffffffu, xb, e) * sWv[l][e];
        // G[h*4+c][o] = sum_d Vb[c][h*4+d] * Wp[o][h*4+d]; store transposed
        #pragma unroll
        for (int h = 0; h < NH; ++h) {
            float gv = 0.0f;
            #pragma unroll
            for (int d = 0; d < 4; ++d)
                gv += __shfl_sync(0xffffffffu, acc, h * 4 + d) * sWp[l][h * 4 + d];
            sGT[l][h * 4 + c] = gv;
        }
    }
    __syncthreads();   // single barrier: covers sP (all warps) and sGT (warps 0-3)

    // ========== Phase 3: z = bp + P . G^T + direct store ==========
    {
        float pr[NE];
        #pragma unroll
        for (int k = 0; k < 8; ++k) {
            const float4 v = *(const float4*)&sP[l][k * 4];
            pr[4*k] = v.x; pr[4*k+1] = v.y; pr[4*k+2] = v.z; pr[4*k+3] = v.w;
        }
        float zv[4];
        #pragma unroll
        for (int i = 0; i < 4; ++i) {
            const int o = o0 + i;                        // warp-uniform
            const float4* grow = (const float4*)&sGT[o][0];
            float a = sbp[o];
            #pragma unroll
            for (int k = 0; k < 8; ++k) {
                const float4 v = grow[k];                // broadcast LDS.128
                a += pr[4*k] * v.x + pr[4*k+1] * v.y
                   + pr[4*k+2] * v.z + pr[4*k+3] * v.w;
            }
            zv[i] = a;
        }
        // direct 16B store: row tg0+l, cols [o0, o0+4)
        *(float4*)(out + ((size_t)(tg0 + l)) * NE + o0) =
            make_float4(zv[0], zv[1], zv[2], zv[3]);
    }
}

extern "C" void kernel_launch(void* const* d_in, const int* in_sizes, int n_in,
                              void* d_out, int out_size)
{
    // metadata order: x, Wq, bq, Wk, bk, Wv, bv, Wp, bp   (Wk/bk dead)
    const float* x  = (const float*)d_in[0];
    const float* Wq = (const float*)d_in[1];
    const float* bq = (const float*)d_in[2];
    const float* Wv = (const float*)d_in[5];
    const float* bv = (const float*)d_in[6];
    const float* Wp = (const float*)d_in[7];
    const float* bp = (const float*)d_in[8];
    float* out = (float*)d_out;

    xpart_kernel<<<BB * NSLICE, 128>>>(x);

    // Kernel B with programmatic dependent launch: overlaps A entirely;
    // the griddep wait sits AFTER softmax, ~5us into B, so it never stalls.
    cudaLaunchConfig_t cfg = {};
    cfg.gridDim  = dim3(NCTA_B, 1, 1);
    cfg.blockDim = dim3(THR_B, 1, 1);
    cfg.dynamicSmemBytes = 0;
    cfg.stream = 0;
    cudaLaunchAttribute attrs[1];
    attrs[0].id = cudaLaunchAttributeProgrammaticStreamSerialization;
    attrs[0].val.programmaticStreamSerializationAllowed = 1;
    cfg.attrs = attrs;
    cfg.numAttrs = 1;
    cudaLaunchKernelEx(&cfg, rxtx_attn_kernel, x, Wq, bq, Wv, bv, Wp, bp, out);
}